// round 13
// baseline (speedup 1.0000x reference)
#include <cuda_runtime.h>
#include <cuda_bf16.h>
#include <cstdint>

#define EPS_BN 1e-5f

#define BATCH   32
#define CIN     128
#define COUT    256
#define CEXP    1024
#define HOUT    28
#define HWOUT   784
#define MPIX    25088          // BATCH*HWOUT, divisible by 128
#define KL1     512            // conv1 logical K (CIN*2*2)

// ------------- scratch (device globals) -------------------------------------
// split activations: row 2k = bf16 hi, row 2k+1 = bf16 lo of logical k-row
__device__ __nv_bfloat16 g_A [(size_t)2 * KL1  * MPIX];   // conv1 A   (51.4 MB)
__device__ float         g_t0[(size_t)BATCH * COUT * HWOUT]; // conv1 out NCHW
__device__ __nv_bfloat16 g_t1[(size_t)2 * COUT * MPIX];   // dw out    (25.7 MB)
__device__ __nv_bfloat16 g_t2[(size_t)2 * CEXP * MPIX];   // expand out(102.8 MB)
__device__ __nv_bfloat16 g_Wd[2 * KL1  * COUT];           // 15*w, dup rows
__device__ float         g_W1f[COUT * 49];
__device__ __nv_bfloat16 g_W2[2 * COUT * CEXP];
__device__ __nv_bfloat16 g_W3[2 * CEXP * COUT];
__device__ unsigned g_max[4];

// ------------- helpers -------------------------------------------------------
__device__ __forceinline__ void ldmx4t(uint32_t& r0, uint32_t& r1, uint32_t& r2,
                                       uint32_t& r3, uint32_t addr) {
    asm volatile("ldmatrix.sync.aligned.m8n8.x4.trans.shared.b16 {%0,%1,%2,%3},[%4];"
                 : "=r"(r0), "=r"(r1), "=r"(r2), "=r"(r3) : "r"(addr));
}

__device__ __forceinline__ void mma16816(float c[4], const uint32_t a[4],
                                         uint32_t b0, uint32_t b1) {
    asm volatile("mma.sync.aligned.m16n8k16.row.col.f32.bf16.bf16.f32 "
                 "{%0,%1,%2,%3},{%4,%5,%6,%7},{%8,%9},{%0,%1,%2,%3};"
                 : "+f"(c[0]), "+f"(c[1]), "+f"(c[2]), "+f"(c[3])
                 : "r"(a[0]), "r"(a[1]), "r"(a[2]), "r"(a[3]), "r"(b0), "r"(b1));
}

__device__ __forceinline__ void cp16(uint32_t s, const void* g) {
    asm volatile("cp.async.cg.shared.global [%0],[%1],16;\n" :: "r"(s), "l"(g));
}
#define CP_COMMIT() asm volatile("cp.async.commit_group;\n")

// ------------- weight quantization -------------------------------------------
__global__ void max4_kernel(const float* __restrict__ w0, const float* __restrict__ w1,
                            const float* __restrict__ w2, const float* __restrict__ w3) {
    int slot = blockIdx.y;
    const float* w; int n;
    if      (slot == 0) { w = w0; n = COUT * KL1; }
    else if (slot == 1) { w = w1; n = COUT * 49; }
    else if (slot == 2) { w = w2; n = CEXP * COUT; }
    else                { w = w3; n = COUT * CEXP; }
    float lm = 0.f;
    for (int i = blockIdx.x * blockDim.x + threadIdx.x; i < n;
         i += gridDim.x * blockDim.x)
        lm = fmaxf(lm, fabsf(tanhf(w[i])));
    #pragma unroll
    for (int o = 16; o > 0; o >>= 1)
        lm = fmaxf(lm, __shfl_xor_sync(0xffffffffu, lm, o));
    if ((threadIdx.x & 31) == 0) atomicMax(&g_max[slot], __float_as_uint(lm));
}

// y=0: Wd, y=1: W2, y=2: W3 -> scaled (15*w) bf16, [2K][N] dup rows
// y=3: W1 -> fp32 true quantized values
__global__ void quantW_all(const float* __restrict__ Wd, const float* __restrict__ W2,
                           const float* __restrict__ W3, const float* __restrict__ W1) {
    int which = blockIdx.y;
    int i = blockIdx.x * 256 + threadIdx.x;
    if (which == 3) {
        if (i >= COUT * 49) return;
        float mx = __uint_as_float(g_max[1]);
        float t = tanhf(W1[i]) / (2.f * mx) + 0.5f;
        g_W1f[i] = 2.f * (rintf(t * 15.f) / 15.f) - 1.f;
        return;
    }
    const float* src; __nv_bfloat16* dst; int N, K, slot;
    if      (which == 0) { src = Wd; dst = g_Wd; N = COUT; K = KL1;  slot = 0; }
    else if (which == 1) { src = W2; dst = g_W2; N = CEXP; K = COUT; slot = 2; }
    else                 { src = W3; dst = g_W3; N = COUT; K = CEXP; slot = 3; }
    if (i >= N * K) return;
    int n = i / K, k = i - n * K;
    float mx = __uint_as_float(g_max[slot]);
    float t  = tanhf(src[i]) / (2.f * mx) + 0.5f;
    __nv_bfloat16 v = __float2bfloat16(2.f * rintf(t * 15.f) - 15.f);  // odd int, exact
    dst[(size_t)(2 * k) * N + n] = v;
    dst[(size_t)(2 * k + 1) * N + n] = v;
}

// ------------- BN0 + q16 + im2col -> split bf16 rows -------------------------
__global__ void im2col_kernel(const float* __restrict__ x,
                              const float* __restrict__ bg, const float* __restrict__ bb,
                              const float* __restrict__ bm, const float* __restrict__ bv) {
    int m = blockIdx.x * 256 + threadIdx.x;   // gridDim.x = 98 -> exactly MPIX
    int cd = blockIdx.y;                      // 0..255
    int c = cd >> 1, dy = cd & 1;
    int b = m / HWOUT, s = m - b * HWOUT;
    int oh = s / HOUT, ow = s - oh * HOUT;
    float2 v2 = *(const float2*)(x + (((size_t)b * CIN + c) * 56 + oh * 2 + dy) * 56
                                   + ow * 2);
    float inv  = bg[c] / sqrtf(bv[c] + EPS_BN);
    float bias = bb[c] - bm[c] * inv;
    int kbase = 4 * c + 2 * dy;
    #pragma unroll
    for (int dx = 0; dx < 2; dx++) {
        float v = dx ? v2.y : v2.x;
        float y = fminf(fmaxf(v * inv + bias, 0.f), 1.f);
        y = rintf(y * 65535.f) / 65535.f;
        __nv_bfloat16 h = __float2bfloat16(y);
        int k = kbase + dx;
        g_A[(size_t)(2 * k) * MPIX + m]     = h;
        g_A[(size_t)(2 * k + 1) * MPIX + m] = __float2bfloat16(y - __bfloat162float(h));
    }
}

// ------------- tensor-core GEMM, 128x64 tile, 3 CTAs/SM ----------------------
// Grid: blockIdx.x = n-tile (fast -> L2 reuse of A), blockIdx.y = m-tile.
// C[m][n] = (1/15) * sum_{k'} A[k'][m] * B[k'][n],  Kp = k' rows
// MODE 0: write fp32 NCHW        (conv1)
// MODE 1: relu -> split bf16 [2n][M] (expand)
// MODE 2: +resid NCHW, clip, q4 -> fp32 NCHW (project)
#define BM 128
#define BN 64
#define BK 32
#define LDSA 136    // A row stride in bf16 (272B)
#define LDSB 72     // B row stride in bf16 (144B) -> 4-bank rotation, conflict-free
#define STAGES 4
#define A_BYTES (BK * LDSA * 2)           // 8704
#define B_BYTES (BK * LDSB * 2)           // 4608
#define STG_BYTES (A_BYTES + B_BYTES)     // 13312
#define SM_GEMM (STAGES * STG_BYTES)      // 53248 (>= 128*65*4 = 33280 staging)

template<int MODE>
__global__ void __launch_bounds__(256, 3)
mma_gemm(const __nv_bfloat16* __restrict__ A, const __nv_bfloat16* __restrict__ B,
         int Kp, int N, float* __restrict__ outf, __nv_bfloat16* __restrict__ outp,
         const float* __restrict__ resid) {
    extern __shared__ char smem[];
    const int tid = threadIdx.x;
    const int lane = tid & 31, wid = tid >> 5;
    const int m0b = blockIdx.y * BM, n0b = blockIdx.x * BN;
    const int wm = (wid & 1) * 64;         // 2 m-warps
    const int wn = (wid >> 1) * 16;        // 4 n-warps, 16 cols each

    float acc[4][2][4];                    // 32 regs
    #pragma unroll
    for (int t = 0; t < 4; t++)
        #pragma unroll
        for (int u = 0; u < 2; u++)
            #pragma unroll
            for (int e = 0; e < 4; e++) acc[t][u][e] = 0.f;

    // global->shared: A two cp16 (rows tid>>4, +16), B one cp16 (row tid>>3)
    const int ra = tid >> 4, ca = (tid & 15) * 8;
    const int rb = tid >> 3, cb = (tid & 7) * 8;

    const uint32_t sbase = (uint32_t)__cvta_generic_to_shared(smem);
    const uint32_t a_off = (ra * LDSA + ca) * 2;
    const uint32_t b_off = (rb * LDSB + cb) * 2;

    const int g = lane >> 3, r = lane & 7;
    const int a_row0 = ((g >> 1) << 3) + r;
    const int a_col  = wm + ((g & 1) << 3);
    const int b_row0 = ((g & 1) << 3) + r;
    const int b_col0 = wn + ((g >> 1) << 3);

    const int iters = Kp / BK;

    auto load_tile = [&](int it) {
        if (it < iters) {
            const int kb = it * BK;
            const uint32_t sa = sbase + (it % STAGES) * STG_BYTES;
            const __nv_bfloat16* ag = A + (size_t)(kb + ra) * MPIX + m0b + ca;
            cp16(sa + a_off, ag);
            cp16(sa + a_off + 16 * LDSA * 2, ag + (size_t)16 * MPIX);
            cp16(sa + A_BYTES + b_off, B + (size_t)(kb + rb) * N + n0b + cb);
        }
        CP_COMMIT();   // always commit to keep group count invariant
    };

    load_tile(0);
    load_tile(1);
    load_tile(2);

    for (int it = 0; it < iters; ++it) {
        asm volatile("cp.async.wait_group 2;\n");
        __syncthreads();
        load_tile(it + 3);   // overwrites slot of tile it-1 (computed last iter)

        const uint32_t ab = sbase + (it % STAGES) * STG_BYTES;
        const uint32_t bb = ab + A_BYTES;
        #pragma unroll
        for (int h = 0; h < 2; ++h) {
            uint32_t af[4][4];
            #pragma unroll
            for (int t = 0; t < 4; ++t)
                ldmx4t(af[t][0], af[t][1], af[t][2], af[t][3],
                       ab + ((a_row0 + h * 16) * LDSA + a_col + t * 16) * 2);
            uint32_t bfr[4];
            ldmx4t(bfr[0], bfr[1], bfr[2], bfr[3],
                   bb + ((b_row0 + h * 16) * LDSB + b_col0) * 2);
            #pragma unroll
            for (int t = 0; t < 4; ++t)
                #pragma unroll
                for (int u = 0; u < 2; ++u)
                    mma16816(acc[t][u], af[t], bfr[u * 2], bfr[u * 2 + 1]);
        }
    }

    // ---------- epilogue: stage via smem, write coalesced --------------------
    asm volatile("cp.async.wait_group 0;\n");
    __syncthreads();
    float* st = (float*)smem;                 // [128][65] fp32
    const float SC = 1.f / 15.f;
    const int row_ = lane >> 2, col_ = (lane & 3) * 2;
    #pragma unroll
    for (int t = 0; t < 4; ++t)
        #pragma unroll
        for (int u = 0; u < 2; ++u)
            #pragma unroll
            for (int e = 0; e < 4; ++e) {
                int ml = wm + t * 16 + row_ + ((e >> 1) ? 8 : 0);
                int nl = wn + u * 8 + col_ + (e & 1);
                st[ml * 65 + nl] = acc[t][u][e] * SC;
            }
    __syncthreads();

    // each warp owns 8 n-rows; per n, lanes cover contiguous m (coalesced)
    #pragma unroll 1
    for (int q = 0; q < 8; ++q) {
        int nl = wid * 8 + q;
        int n = n0b + nl;
        if (MODE == 1) {
            #pragma unroll
            for (int j = 0; j < 4; ++j) {
                int ml = j * 32 + lane;
                float v = fmaxf(st[ml * 65 + nl], 0.f);
                __nv_bfloat16 h = __float2bfloat16(v);
                int m = m0b + ml;
                outp[(size_t)(2 * n) * MPIX + m] = h;
                outp[(size_t)(2 * n + 1) * MPIX + m] =
                    __float2bfloat16(v - __bfloat162float(h));
            }
        } else {
            #pragma unroll
            for (int j = 0; j < 4; ++j) {
                int ml = j * 32 + lane;
                int m = m0b + ml;
                int b = m / HWOUT, s = m - b * HWOUT;
                size_t idx = ((size_t)b * COUT + n) * HWOUT + s;
                float v = st[ml * 65 + nl];
                if (MODE == 0) {
                    outf[idx] = v;
                } else {
                    v += resid[idx];
                    v = fminf(fmaxf(v, 0.f), 1.f);
                    outf[idx] = rintf(v * 15.f) * SC;
                }
            }
        }
    }
}

// ------------- depthwise 7x7 + BN1 -> split bf16 -----------------------------
__global__ void dwconv_kernel(const float* __restrict__ bg, const float* __restrict__ bb,
                              const float* __restrict__ bm, const float* __restrict__ bv) {
    __shared__ float tile[34 * 34];
    __shared__ float w[49];
    int bc = blockIdx.x;
    int c = bc & (COUT - 1);
    int b = bc >> 8;
    const float* plane = g_t0 + (size_t)bc * HWOUT;
    int tid = threadIdx.x;
    for (int idx = tid; idx < 34 * 34; idx += 256) {
        int rr = idx / 34, cc = idx - rr * 34;
        int ih = rr - 3, iw = cc - 3;
        tile[idx] = (ih >= 0 && ih < HOUT && iw >= 0 && iw < HOUT)
                        ? plane[ih * HOUT + iw] : 0.f;
    }
    if (tid < 49) w[tid] = g_W1f[c * 49 + tid];
    __syncthreads();
    float inv  = bg[c] / sqrtf(bv[c] + EPS_BN);
    float bias = bb[c] - bm[c] * inv;
    for (int s = tid; s < HWOUT; s += 256) {
        int oh = s / HOUT, ow = s - oh * HOUT;
        float sum = 0.f;
        #pragma unroll
        for (int i = 0; i < 7; i++)
            #pragma unroll
            for (int j = 0; j < 7; j++)
                sum = fmaf(tile[(oh + i) * 34 + ow + j], w[i * 7 + j], sum);
        float y = sum * inv + bias;
        __nv_bfloat16 h = __float2bfloat16(y);
        int m = b * HWOUT + s;
        g_t1[(size_t)(2 * c) * MPIX + m]     = h;
        g_t1[(size_t)(2 * c + 1) * MPIX + m] = __float2bfloat16(y - __bfloat162float(h));
    }
}

// ------------- launch --------------------------------------------------------
extern "C" void kernel_launch(void* const* d_in, const int* in_sizes, int n_in,
                              void* d_out, int out_size) {
    const float* x     = (const float*)d_in[0];
    const float* bn0_g = (const float*)d_in[1];
    const float* bn0_b = (const float*)d_in[2];
    const float* bn0_m = (const float*)d_in[3];
    const float* bn0_v = (const float*)d_in[4];
    const float* Wd    = (const float*)d_in[5];
    const float* W1    = (const float*)d_in[6];
    const float* bn1_g = (const float*)d_in[7];
    const float* bn1_b = (const float*)d_in[8];
    const float* bn1_m = (const float*)d_in[9];
    const float* bn1_v = (const float*)d_in[10];
    const float* W2    = (const float*)d_in[11];
    const float* W3    = (const float*)d_in[12];
    float* out = (float*)d_out;

    void *pA, *pT0, *pT1, *pT2, *pWd, *pW2, *pW3, *pMax;
    cudaGetSymbolAddress(&pA,  g_A);
    cudaGetSymbolAddress(&pT0, g_t0);
    cudaGetSymbolAddress(&pT1, g_t1);
    cudaGetSymbolAddress(&pT2, g_t2);
    cudaGetSymbolAddress(&pWd, g_Wd);
    cudaGetSymbolAddress(&pW2, g_W2);
    cudaGetSymbolAddress(&pW3, g_W3);
    cudaGetSymbolAddress(&pMax, g_max);

    cudaFuncSetAttribute(mma_gemm<0>, cudaFuncAttributeMaxDynamicSharedMemorySize, SM_GEMM);
    cudaFuncSetAttribute(mma_gemm<1>, cudaFuncAttributeMaxDynamicSharedMemorySize, SM_GEMM);
    cudaFuncSetAttribute(mma_gemm<2>, cudaFuncAttributeMaxDynamicSharedMemorySize, SM_GEMM);

    // weight quantization
    cudaMemsetAsync(pMax, 0, 16);
    max4_kernel<<<dim3(64, 4), 256>>>(Wd, W1, W2, W3);
    quantW_all<<<dim3(1024, 4), 256>>>(Wd, W2, W3, W1);

    // BN0 + q16 + im2col (split bf16)
    im2col_kernel<<<dim3(98, 256), 256>>>(x, bn0_g, bn0_b, bn0_m, bn0_v);

    // conv1: M=25088, N=256, Kp=1024  (grid: n fast, m slow)
    mma_gemm<0><<<dim3(COUT / BN, MPIX / BM), 256, SM_GEMM>>>(
        (const __nv_bfloat16*)pA, (const __nv_bfloat16*)pWd, 2 * KL1, COUT,
        (float*)pT0, nullptr, nullptr);

    // depthwise + BN1
    dwconv_kernel<<<BATCH * COUT, 256>>>(bn1_g, bn1_b, bn1_m, bn1_v);

    // expand: N=1024, Kp=512
    mma_gemm<1><<<dim3(CEXP / BN, MPIX / BM), 256, SM_GEMM>>>(
        (const __nv_bfloat16*)pT1, (const __nv_bfloat16*)pW2, 2 * COUT, CEXP,
        nullptr, (__nv_bfloat16*)pT2, nullptr);

    // project: N=256, Kp=2048, + residual + q4
    mma_gemm<2><<<dim3(COUT / BN, MPIX / BM), 256, SM_GEMM>>>(
        (const __nv_bfloat16*)pT2, (const __nv_bfloat16*)pW3, 2 * CEXP, COUT,
        out, nullptr, (const float*)pT0);
}

// round 14
// speedup vs baseline: 1.0740x; 1.0740x over previous
#include <cuda_runtime.h>
#include <cuda_bf16.h>
#include <cstdint>

#define EPS_BN 1e-5f

#define BATCH   32
#define CIN     128
#define COUT    256
#define CEXP    1024
#define HOUT    28
#define HWOUT   784
#define MPIX    25088          // BATCH*HWOUT, divisible by 128
#define KL1     512            // conv1 logical K (CIN*2*2)

// ------------- scratch (device globals) -------------------------------------
// activations: TWO planes, hi [K][M] then lo [K][M]
__device__ __nv_bfloat16 g_A [(size_t)2 * KL1  * MPIX];   // conv1 A   (51.4 MB)
__device__ float         g_t0[(size_t)BATCH * COUT * HWOUT]; // conv1 out NCHW
__device__ __nv_bfloat16 g_t1[(size_t)2 * COUT * MPIX];   // dw out planes
__device__ __nv_bfloat16 g_t2[(size_t)2 * CEXP * MPIX];   // expand out planes
__device__ __nv_bfloat16 g_Wd[KL1  * COUT];               // 15*w, [K][N], no dup
__device__ float         g_W1f[COUT * 49];
__device__ __nv_bfloat16 g_W2[COUT * CEXP];
__device__ __nv_bfloat16 g_W3[CEXP * COUT];
__device__ unsigned g_max[4];

// ------------- helpers -------------------------------------------------------
__device__ __forceinline__ void ldmx4t(uint32_t& r0, uint32_t& r1, uint32_t& r2,
                                       uint32_t& r3, uint32_t addr) {
    asm volatile("ldmatrix.sync.aligned.m8n8.x4.trans.shared.b16 {%0,%1,%2,%3},[%4];"
                 : "=r"(r0), "=r"(r1), "=r"(r2), "=r"(r3) : "r"(addr));
}

__device__ __forceinline__ void mma16816(float c[4], const uint32_t a[4],
                                         uint32_t b0, uint32_t b1) {
    asm volatile("mma.sync.aligned.m16n8k16.row.col.f32.bf16.bf16.f32 "
                 "{%0,%1,%2,%3},{%4,%5,%6,%7},{%8,%9},{%0,%1,%2,%3};"
                 : "+f"(c[0]), "+f"(c[1]), "+f"(c[2]), "+f"(c[3])
                 : "r"(a[0]), "r"(a[1]), "r"(a[2]), "r"(a[3]), "r"(b0), "r"(b1));
}

__device__ __forceinline__ void cp16(uint32_t s, const void* g) {
    asm volatile("cp.async.cg.shared.global [%0],[%1],16;\n" :: "r"(s), "l"(g));
}
#define CP_COMMIT() asm volatile("cp.async.commit_group;\n")

// ------------- weight quantization -------------------------------------------
__global__ void max4_kernel(const float* __restrict__ w0, const float* __restrict__ w1,
                            const float* __restrict__ w2, const float* __restrict__ w3) {
    int slot = blockIdx.y;
    const float* w; int n;
    if      (slot == 0) { w = w0; n = COUT * KL1; }
    else if (slot == 1) { w = w1; n = COUT * 49; }
    else if (slot == 2) { w = w2; n = CEXP * COUT; }
    else                { w = w3; n = COUT * CEXP; }
    float lm = 0.f;
    for (int i = blockIdx.x * blockDim.x + threadIdx.x; i < n;
         i += gridDim.x * blockDim.x)
        lm = fmaxf(lm, fabsf(tanhf(w[i])));
    #pragma unroll
    for (int o = 16; o > 0; o >>= 1)
        lm = fmaxf(lm, __shfl_xor_sync(0xffffffffu, lm, o));
    if ((threadIdx.x & 31) == 0) atomicMax(&g_max[slot], __float_as_uint(lm));
}

// y=0: Wd, y=1: W2, y=2: W3 -> scaled (15*w) bf16, [K][N], NO duplication
// y=3: W1 -> fp32 true quantized values
__global__ void quantW_all(const float* __restrict__ Wd, const float* __restrict__ W2,
                           const float* __restrict__ W3, const float* __restrict__ W1) {
    int which = blockIdx.y;
    int i = blockIdx.x * 256 + threadIdx.x;
    if (which == 3) {
        if (i >= COUT * 49) return;
        float mx = __uint_as_float(g_max[1]);
        float t = tanhf(W1[i]) / (2.f * mx) + 0.5f;
        g_W1f[i] = 2.f * (rintf(t * 15.f) / 15.f) - 1.f;
        return;
    }
    const float* src; __nv_bfloat16* dst; int N, K, slot;
    if      (which == 0) { src = Wd; dst = g_Wd; N = COUT; K = KL1;  slot = 0; }
    else if (which == 1) { src = W2; dst = g_W2; N = CEXP; K = COUT; slot = 2; }
    else                 { src = W3; dst = g_W3; N = COUT; K = CEXP; slot = 3; }
    if (i >= N * K) return;
    int n = i / K, k = i - n * K;
    float mx = __uint_as_float(g_max[slot]);
    float t  = tanhf(src[i]) / (2.f * mx) + 0.5f;
    dst[(size_t)k * N + n] = __float2bfloat16(2.f * rintf(t * 15.f) - 15.f);
}

// ------------- BN0 + q16 + im2col -> hi/lo planes ----------------------------
__global__ void im2col_kernel(const float* __restrict__ x,
                              const float* __restrict__ bg, const float* __restrict__ bb,
                              const float* __restrict__ bm, const float* __restrict__ bv) {
    int m = blockIdx.x * 256 + threadIdx.x;   // gridDim.x = 98 -> exactly MPIX
    int cd = blockIdx.y;                      // 0..255
    int c = cd >> 1, dy = cd & 1;
    int b = m / HWOUT, s = m - b * HWOUT;
    int oh = s / HOUT, ow = s - oh * HOUT;
    float2 v2 = *(const float2*)(x + (((size_t)b * CIN + c) * 56 + oh * 2 + dy) * 56
                                   + ow * 2);
    float inv  = bg[c] / sqrtf(bv[c] + EPS_BN);
    float bias = bb[c] - bm[c] * inv;
    int kbase = 4 * c + 2 * dy;
    #pragma unroll
    for (int dx = 0; dx < 2; dx++) {
        float v = dx ? v2.y : v2.x;
        float y = fminf(fmaxf(v * inv + bias, 0.f), 1.f);
        y = rintf(y * 65535.f) / 65535.f;
        __nv_bfloat16 h = __float2bfloat16(y);
        int k = kbase + dx;
        g_A[(size_t)k * MPIX + m] = h;                                   // hi plane
        g_A[(size_t)(KL1 + k) * MPIX + m] =
            __float2bfloat16(y - __bfloat162float(h));                    // lo plane
    }
}

// ------------- tensor-core GEMM: hi/lo planes share B fragments --------------
// Grid: blockIdx.x = n-tile (fast -> L2 reuse of A), blockIdx.y = m-tile.
// C[m][n] = (1/15) * sum_k (Ahi[k][m]+Alo[k][m]) * B[k][n],  K logical rows
// MODE 0: write fp32 NCHW        (conv1)
// MODE 1: relu -> hi/lo planes [2][N][M] (expand)
// MODE 2: +resid NCHW, clip, q4 -> fp32 NCHW (project)
#define BM 128
#define BN 128
#define BKL 16      // logical k per iteration (32 A rows: 16 hi + 16 lo; 16 B rows)
#define LDSA 136    // row stride bf16 (272B), ldmatrix conflict-free
#define STAGES 4
#define A_BYTES (32 * LDSA * 2)           // 8704  (16 hi + 16 lo rows)
#define B_BYTES (16 * LDSA * 2)           // 4352
#define STG_BYTES (A_BYTES + B_BYTES)     // 13056
#define SM_GEMM 66560                     // >= 4*13056=52224 and >= 128*129*4=66048

template<int MODE>
__global__ void __launch_bounds__(256)
mma_gemm(const __nv_bfloat16* __restrict__ A, size_t aplane,
         const __nv_bfloat16* __restrict__ B,
         int K, int N, float* __restrict__ outf, __nv_bfloat16* __restrict__ outp,
         const float* __restrict__ resid) {
    extern __shared__ char smem[];
    const int tid = threadIdx.x;
    const int lane = tid & 31, wid = tid >> 5;
    const int m0b = blockIdx.y * BM, n0b = blockIdx.x * BN;
    const int wm = (wid & 1) * 64;
    const int wn = (wid >> 1) * 32;

    float acc[4][4][4];
    #pragma unroll
    for (int t = 0; t < 4; t++)
        #pragma unroll
        for (int u = 0; u < 4; u++)
            #pragma unroll
            for (int e = 0; e < 4; e++) acc[t][u][e] = 0.f;

    // loaders: A hi row ra -> smem row ra; A lo row ra -> smem row 16+ra;
    //          B row ra -> B area row ra.  One cp16 each (3/thread).
    const int ra = tid >> 4, ca = (tid & 15) * 8;
    const uint32_t sbase = (uint32_t)__cvta_generic_to_shared(smem);
    const uint32_t a_off = (ra * LDSA + ca) * 2;

    const int g = lane >> 3, r = lane & 7;
    const int a_row0 = ((g >> 1) << 3) + r;          // 0..15
    const int a_col  = wm + ((g & 1) << 3);
    const int b_row0 = ((g & 1) << 3) + r;           // 0..15
    const int b_col0 = wn + ((g >> 1) << 3);

    const int iters = K / BKL;

    auto load_tile = [&](int it) {
        if (it < iters) {
            const int kb = it * BKL;
            const uint32_t sa = sbase + (it % STAGES) * STG_BYTES;
            const __nv_bfloat16* ag = A + (size_t)(kb + ra) * MPIX + m0b + ca;
            cp16(sa + a_off, ag);                                  // hi
            cp16(sa + a_off + 16 * LDSA * 2, ag + aplane);         // lo
            cp16(sa + A_BYTES + a_off, B + (size_t)(kb + ra) * N + n0b + ca);
        }
        CP_COMMIT();   // always commit to keep group count invariant
    };

    load_tile(0);
    load_tile(1);
    load_tile(2);

    for (int it = 0; it < iters; ++it) {
        asm volatile("cp.async.wait_group 2;\n");
        __syncthreads();
        load_tile(it + 3);   // overwrites slot of tile it-1 (computed last iter)

        const uint32_t ab = sbase + (it % STAGES) * STG_BYTES;
        const uint32_t bb = ab + A_BYTES;
        uint32_t bfr[2][4];
        #pragma unroll
        for (int pq = 0; pq < 2; ++pq)
            ldmx4t(bfr[pq][0], bfr[pq][1], bfr[pq][2], bfr[pq][3],
                   bb + (b_row0 * LDSA + b_col0 + pq * 16) * 2);
        #pragma unroll
        for (int pl = 0; pl < 2; ++pl) {             // 0 = hi rows, 1 = lo rows
            uint32_t af[4][4];
            #pragma unroll
            for (int t = 0; t < 4; ++t)
                ldmx4t(af[t][0], af[t][1], af[t][2], af[t][3],
                       ab + ((pl * 16 + a_row0) * LDSA + a_col + t * 16) * 2);
            #pragma unroll
            for (int t = 0; t < 4; ++t)
                #pragma unroll
                for (int u = 0; u < 4; ++u)
                    mma16816(acc[t][u], af[t],
                             bfr[u >> 1][(u & 1) * 2], bfr[u >> 1][(u & 1) * 2 + 1]);
        }
    }

    // ---------- epilogue: stage via smem, write coalesced --------------------
    asm volatile("cp.async.wait_group 0;\n");
    __syncthreads();
    float* st = (float*)smem;                 // [128][129] fp32
    const float SC = 1.f / 15.f;
    const int row_ = lane >> 2, col_ = (lane & 3) * 2;
    #pragma unroll
    for (int t = 0; t < 4; ++t)
        #pragma unroll
        for (int u = 0; u < 4; ++u)
            #pragma unroll
            for (int e = 0; e < 4; ++e) {
                int ml = wm + t * 16 + row_ + ((e >> 1) ? 8 : 0);
                int nl = wn + u * 8 + col_ + (e & 1);
                st[ml * 129 + nl] = acc[t][u][e] * SC;
            }
    __syncthreads();

    // each warp owns 16 n-rows; per n, lanes cover contiguous m (coalesced)
    #pragma unroll 1
    for (int q = 0; q < 16; ++q) {
        int nl = wid * 16 + q;
        int n = n0b + nl;
        if (MODE == 1) {
            #pragma unroll
            for (int j = 0; j < 4; ++j) {
                int ml = j * 32 + lane;
                float v = fmaxf(st[ml * 129 + nl], 0.f);
                __nv_bfloat16 h = __float2bfloat16(v);
                int m = m0b + ml;
                outp[(size_t)n * MPIX + m] = h;                       // hi plane
                outp[(size_t)(N + n) * MPIX + m] =
                    __float2bfloat16(v - __bfloat162float(h));         // lo plane
            }
        } else {
            #pragma unroll
            for (int j = 0; j < 4; ++j) {
                int ml = j * 32 + lane;
                int m = m0b + ml;
                int b = m / HWOUT, s = m - b * HWOUT;
                size_t idx = ((size_t)b * COUT + n) * HWOUT + s;
                float v = st[ml * 129 + nl];
                if (MODE == 0) {
                    outf[idx] = v;
                } else {
                    v += resid[idx];
                    v = fminf(fmaxf(v, 0.f), 1.f);
                    outf[idx] = rintf(v * 15.f) * SC;
                }
            }
        }
    }
}

// ------------- depthwise 7x7 + BN1 -> hi/lo planes ---------------------------
__global__ void dwconv_kernel(const float* __restrict__ bg, const float* __restrict__ bb,
                              const float* __restrict__ bm, const float* __restrict__ bv) {
    __shared__ float tile[34 * 34];
    __shared__ float w[49];
    int bc = blockIdx.x;
    int c = bc & (COUT - 1);
    int b = bc >> 8;
    const float* plane = g_t0 + (size_t)bc * HWOUT;
    int tid = threadIdx.x;
    for (int idx = tid; idx < 34 * 34; idx += 256) {
        int rr = idx / 34, cc = idx - rr * 34;
        int ih = rr - 3, iw = cc - 3;
        tile[idx] = (ih >= 0 && ih < HOUT && iw >= 0 && iw < HOUT)
                        ? plane[ih * HOUT + iw] : 0.f;
    }
    if (tid < 49) w[tid] = g_W1f[c * 49 + tid];
    __syncthreads();
    float inv  = bg[c] / sqrtf(bv[c] + EPS_BN);
    float bias = bb[c] - bm[c] * inv;
    for (int s = tid; s < HWOUT; s += 256) {
        int oh = s / HOUT, ow = s - oh * HOUT;
        float sum = 0.f;
        #pragma unroll
        for (int i = 0; i < 7; i++)
            #pragma unroll
            for (int j = 0; j < 7; j++)
                sum = fmaf(tile[(oh + i) * 34 + ow + j], w[i * 7 + j], sum);
        float y = sum * inv + bias;
        __nv_bfloat16 h = __float2bfloat16(y);
        int m = b * HWOUT + s;
        g_t1[(size_t)c * MPIX + m] = h;                                  // hi plane
        g_t1[(size_t)(COUT + c) * MPIX + m] =
            __float2bfloat16(y - __bfloat162float(h));                    // lo plane
    }
}

// ------------- launch --------------------------------------------------------
extern "C" void kernel_launch(void* const* d_in, const int* in_sizes, int n_in,
                              void* d_out, int out_size) {
    const float* x     = (const float*)d_in[0];
    const float* bn0_g = (const float*)d_in[1];
    const float* bn0_b = (const float*)d_in[2];
    const float* bn0_m = (const float*)d_in[3];
    const float* bn0_v = (const float*)d_in[4];
    const float* Wd    = (const float*)d_in[5];
    const float* W1    = (const float*)d_in[6];
    const float* bn1_g = (const float*)d_in[7];
    const float* bn1_b = (const float*)d_in[8];
    const float* bn1_m = (const float*)d_in[9];
    const float* bn1_v = (const float*)d_in[10];
    const float* W2    = (const float*)d_in[11];
    const float* W3    = (const float*)d_in[12];
    float* out = (float*)d_out;

    void *pA, *pT0, *pT1, *pT2, *pWd, *pW2, *pW3, *pMax;
    cudaGetSymbolAddress(&pA,  g_A);
    cudaGetSymbolAddress(&pT0, g_t0);
    cudaGetSymbolAddress(&pT1, g_t1);
    cudaGetSymbolAddress(&pT2, g_t2);
    cudaGetSymbolAddress(&pWd, g_Wd);
    cudaGetSymbolAddress(&pW2, g_W2);
    cudaGetSymbolAddress(&pW3, g_W3);
    cudaGetSymbolAddress(&pMax, g_max);

    cudaFuncSetAttribute(mma_gemm<0>, cudaFuncAttributeMaxDynamicSharedMemorySize, SM_GEMM);
    cudaFuncSetAttribute(mma_gemm<1>, cudaFuncAttributeMaxDynamicSharedMemorySize, SM_GEMM);
    cudaFuncSetAttribute(mma_gemm<2>, cudaFuncAttributeMaxDynamicSharedMemorySize, SM_GEMM);

    // weight quantization
    cudaMemsetAsync(pMax, 0, 16);
    max4_kernel<<<dim3(64, 4), 256>>>(Wd, W1, W2, W3);
    quantW_all<<<dim3(1024, 4), 256>>>(Wd, W2, W3, W1);

    // BN0 + q16 + im2col (hi/lo planes)
    im2col_kernel<<<dim3(98, 256), 256>>>(x, bn0_g, bn0_b, bn0_m, bn0_v);

    // conv1: M=25088, N=256, K=512  (grid: n fast, m slow)
    mma_gemm<0><<<dim3(COUT / BN, MPIX / BM), 256, SM_GEMM>>>(
        (const __nv_bfloat16*)pA, (size_t)KL1 * MPIX, (const __nv_bfloat16*)pWd,
        KL1, COUT, (float*)pT0, nullptr, nullptr);

    // depthwise + BN1
    dwconv_kernel<<<BATCH * COUT, 256>>>(bn1_g, bn1_b, bn1_m, bn1_v);

    // expand: N=1024, K=256
    mma_gemm<1><<<dim3(CEXP / BN, MPIX / BM), 256, SM_GEMM>>>(
        (const __nv_bfloat16*)pT1, (size_t)COUT * MPIX, (const __nv_bfloat16*)pW2,
        COUT, CEXP, nullptr, (__nv_bfloat16*)pT2, nullptr);

    // project: N=256, K=1024, + residual + q4
    mma_gemm<2><<<dim3(COUT / BN, MPIX / BM), 256, SM_GEMM>>>(
        (const __nv_bfloat16*)pT2, (size_t)CEXP * MPIX, (const __nv_bfloat16*)pW3,
        CEXP, COUT, out, nullptr, (const float*)pT0);
}

// round 15
// speedup vs baseline: 1.0954x; 1.0199x over previous
#include <cuda_runtime.h>
#include <cuda_bf16.h>
#include <cstdint>

#define EPS_BN 1e-5f

#define BATCH   32
#define CIN     128
#define COUT    256
#define CEXP    1024
#define HOUT    28
#define HWOUT   784
#define MPIX    25088          // BATCH*HWOUT, divisible by 128
#define KL1     512            // conv1 logical K (CIN*2*2)

// ------------- scratch (device globals) -------------------------------------
// activations: TWO planes, hi [K][M] then lo [K][M]
__device__ __nv_bfloat16 g_A [(size_t)2 * KL1  * MPIX];   // conv1 A   (51.4 MB)
__device__ float         g_t0[(size_t)BATCH * COUT * HWOUT]; // conv1 out NCHW
__device__ __nv_bfloat16 g_t1[(size_t)2 * COUT * MPIX];   // dw out planes
__device__ __nv_bfloat16 g_t2[(size_t)2 * CEXP * MPIX];   // expand out planes
__device__ __nv_bfloat16 g_Wd[KL1  * COUT];               // 15*w, [K][N], no dup
__device__ float         g_W1f[COUT * 49];
__device__ __nv_bfloat16 g_W2[COUT * CEXP];
__device__ __nv_bfloat16 g_W3[CEXP * COUT];
__device__ unsigned g_max[4];

// ------------- helpers -------------------------------------------------------
__device__ __forceinline__ void ldmx4t(uint32_t& r0, uint32_t& r1, uint32_t& r2,
                                       uint32_t& r3, uint32_t addr) {
    asm volatile("ldmatrix.sync.aligned.m8n8.x4.trans.shared.b16 {%0,%1,%2,%3},[%4];"
                 : "=r"(r0), "=r"(r1), "=r"(r2), "=r"(r3) : "r"(addr));
}

__device__ __forceinline__ void mma16816(float c[4], const uint32_t a[4],
                                         uint32_t b0, uint32_t b1) {
    asm volatile("mma.sync.aligned.m16n8k16.row.col.f32.bf16.bf16.f32 "
                 "{%0,%1,%2,%3},{%4,%5,%6,%7},{%8,%9},{%0,%1,%2,%3};"
                 : "+f"(c[0]), "+f"(c[1]), "+f"(c[2]), "+f"(c[3])
                 : "r"(a[0]), "r"(a[1]), "r"(a[2]), "r"(a[3]), "r"(b0), "r"(b1));
}

__device__ __forceinline__ void cp16(uint32_t s, const void* g) {
    asm volatile("cp.async.cg.shared.global [%0],[%1],16;\n" :: "r"(s), "l"(g));
}
#define CP_COMMIT() asm volatile("cp.async.commit_group;\n")

// ------------- weight max (tanh) ---------------------------------------------
__global__ void max4_kernel(const float* __restrict__ w0, const float* __restrict__ w1,
                            const float* __restrict__ w2, const float* __restrict__ w3) {
    int slot = blockIdx.y;
    const float* w; int n;
    if      (slot == 0) { w = w0; n = COUT * KL1; }
    else if (slot == 1) { w = w1; n = COUT * 49; }
    else if (slot == 2) { w = w2; n = CEXP * COUT; }
    else                { w = w3; n = COUT * CEXP; }
    float lm = 0.f;
    for (int i = blockIdx.x * blockDim.x + threadIdx.x; i < n;
         i += gridDim.x * blockDim.x)
        lm = fmaxf(lm, fabsf(tanhf(w[i])));
    #pragma unroll
    for (int o = 16; o > 0; o >>= 1)
        lm = fmaxf(lm, __shfl_xor_sync(0xffffffffu, lm, o));
    if ((threadIdx.x & 31) == 0) atomicMax(&g_max[slot], __float_as_uint(lm));
}

// ------------- fused prep: im2col (y<256) + weight quant (y>=256) ------------
// Independent workloads co-scheduled in one launch. Requires g_max ready.
#define QN_WD (COUT * KL1)          // 131072
#define QN_W2 (CEXP * COUT)         // 262144
#define QN_W3 (COUT * CEXP)         // 262144
#define QN_W1 (COUT * 49)           // 12544
#define QN_TOT (QN_WD + QN_W2 + QN_W3 + QN_W1)   // 667904
#define Q_SLICES ((QN_TOT + MPIX - 1) / MPIX)    // 27

__global__ void prep_kernel(const float* __restrict__ x,
                            const float* __restrict__ bg, const float* __restrict__ bb,
                            const float* __restrict__ bm, const float* __restrict__ bv,
                            const float* __restrict__ Wd, const float* __restrict__ W2,
                            const float* __restrict__ W3, const float* __restrict__ W1) {
    if (blockIdx.y < 256) {
        // ---- im2col: BN0 + q16 -> hi/lo planes ----
        int m = blockIdx.x * 256 + threadIdx.x;   // 98 x-blocks -> exactly MPIX
        int cd = blockIdx.y;
        int c = cd >> 1, dy = cd & 1;
        int b = m / HWOUT, s = m - b * HWOUT;
        int oh = s / HOUT, ow = s - oh * HOUT;
        float2 v2 = *(const float2*)(x + (((size_t)b * CIN + c) * 56 + oh * 2 + dy) * 56
                                       + ow * 2);
        float inv  = bg[c] / sqrtf(bv[c] + EPS_BN);
        float bias = bb[c] - bm[c] * inv;
        int kbase = 4 * c + 2 * dy;
        #pragma unroll
        for (int dx = 0; dx < 2; dx++) {
            float v = dx ? v2.y : v2.x;
            float y = fminf(fmaxf(v * inv + bias, 0.f), 1.f);
            y = rintf(y * 65535.f) / 65535.f;
            __nv_bfloat16 h = __float2bfloat16(y);
            int k = kbase + dx;
            g_A[(size_t)k * MPIX + m] = h;
            g_A[(size_t)(KL1 + k) * MPIX + m] =
                __float2bfloat16(y - __bfloat162float(h));
        }
        return;
    }
    // ---- weight quantization slices ----
    int i = (blockIdx.y - 256) * MPIX + blockIdx.x * 256 + threadIdx.x;
    if (i < QN_WD) {
        float mx = __uint_as_float(g_max[0]);
        int n = i / KL1, k = i - n * KL1;
        float t = tanhf(Wd[i]) / (2.f * mx) + 0.5f;
        g_Wd[(size_t)k * COUT + n] = __float2bfloat16(2.f * rintf(t * 15.f) - 15.f);
        return;
    }
    i -= QN_WD;
    if (i < QN_W2) {
        float mx = __uint_as_float(g_max[2]);
        int n = i / COUT, k = i - n * COUT;
        float t = tanhf(W2[i]) / (2.f * mx) + 0.5f;
        g_W2[(size_t)k * CEXP + n] = __float2bfloat16(2.f * rintf(t * 15.f) - 15.f);
        return;
    }
    i -= QN_W2;
    if (i < QN_W3) {
        float mx = __uint_as_float(g_max[3]);
        int n = i / CEXP, k = i - n * CEXP;
        float t = tanhf(W3[i]) / (2.f * mx) + 0.5f;
        g_W3[(size_t)k * COUT + n] = __float2bfloat16(2.f * rintf(t * 15.f) - 15.f);
        return;
    }
    i -= QN_W3;
    if (i < QN_W1) {
        float mx = __uint_as_float(g_max[1]);
        float t = tanhf(W1[i]) / (2.f * mx) + 0.5f;
        g_W1f[i] = 2.f * (rintf(t * 15.f) / 15.f) - 1.f;
    }
}

// ------------- tensor-core GEMM: hi/lo planes share B fragments --------------
// Grid: blockIdx.x = n-tile (fast -> L2 reuse of A), blockIdx.y = m-tile.
// C[m][n] = (1/15) * sum_k (Ahi[k][m]+Alo[k][m]) * B[k][n]
// MODE 0: write fp32 NCHW        (conv1)
// MODE 1: relu -> hi/lo planes [2][N][M] (expand)
// MODE 2: +resid NCHW, clip, q4 -> fp32 NCHW (project)
#define BM 128
#define BN 128
#define BKL 16      // logical k per iteration (32 A rows: 16 hi + 16 lo; 16 B rows)
#define LDSA 136    // row stride bf16 (272B), ldmatrix conflict-free
#define STAGES 5
#define A_BYTES (32 * LDSA * 2)           // 8704  (16 hi + 16 lo rows)
#define B_BYTES (16 * LDSA * 2)           // 4352
#define STG_BYTES (A_BYTES + B_BYTES)     // 13056
#define SM_GEMM 66560                     // >= 5*13056=65280 and >= 128*129*4=66048

template<int MODE>
__global__ void __launch_bounds__(256)
mma_gemm(const __nv_bfloat16* __restrict__ A, size_t aplane,
         const __nv_bfloat16* __restrict__ B,
         int K, int N, float* __restrict__ outf, __nv_bfloat16* __restrict__ outp,
         const float* __restrict__ resid) {
    extern __shared__ char smem[];
    const int tid = threadIdx.x;
    const int lane = tid & 31, wid = tid >> 5;
    const int m0b = blockIdx.y * BM, n0b = blockIdx.x * BN;
    const int wm = (wid & 1) * 64;
    const int wn = (wid >> 1) * 32;

    float acc[4][4][4];
    #pragma unroll
    for (int t = 0; t < 4; t++)
        #pragma unroll
        for (int u = 0; u < 4; u++)
            #pragma unroll
            for (int e = 0; e < 4; e++) acc[t][u][e] = 0.f;

    const int ra = tid >> 4, ca = (tid & 15) * 8;
    const uint32_t sbase = (uint32_t)__cvta_generic_to_shared(smem);
    const uint32_t a_off = (ra * LDSA + ca) * 2;

    const int g = lane >> 3, r = lane & 7;
    const int a_row0 = ((g >> 1) << 3) + r;          // 0..15
    const int a_col  = wm + ((g & 1) << 3);
    const int b_row0 = ((g & 1) << 3) + r;           // 0..15
    const int b_col0 = wn + ((g >> 1) << 3);

    const int iters = K / BKL;

    auto load_tile = [&](int it) {
        if (it < iters) {
            const int kb = it * BKL;
            const uint32_t sa = sbase + (it % STAGES) * STG_BYTES;
            const __nv_bfloat16* ag = A + (size_t)(kb + ra) * MPIX + m0b + ca;
            cp16(sa + a_off, ag);                                  // hi
            cp16(sa + a_off + 16 * LDSA * 2, ag + aplane);         // lo
            cp16(sa + A_BYTES + a_off, B + (size_t)(kb + ra) * N + n0b + ca);
        }
        CP_COMMIT();   // always commit to keep group count invariant
    };

    load_tile(0);
    load_tile(1);
    load_tile(2);
    load_tile(3);

    for (int it = 0; it < iters; ++it) {
        asm volatile("cp.async.wait_group 3;\n");
        __syncthreads();
        load_tile(it + 4);   // slot (it+4)%5 == slot (it-1)%5, computed last iter

        const uint32_t ab = sbase + (it % STAGES) * STG_BYTES;
        const uint32_t bb = ab + A_BYTES;
        uint32_t bfr[2][4];
        #pragma unroll
        for (int pq = 0; pq < 2; ++pq)
            ldmx4t(bfr[pq][0], bfr[pq][1], bfr[pq][2], bfr[pq][3],
                   bb + (b_row0 * LDSA + b_col0 + pq * 16) * 2);
        #pragma unroll
        for (int pl = 0; pl < 2; ++pl) {             // 0 = hi rows, 1 = lo rows
            uint32_t af[4][4];
            #pragma unroll
            for (int t = 0; t < 4; ++t)
                ldmx4t(af[t][0], af[t][1], af[t][2], af[t][3],
                       ab + ((pl * 16 + a_row0) * LDSA + a_col + t * 16) * 2);
            #pragma unroll
            for (int t = 0; t < 4; ++t)
                #pragma unroll
                for (int u = 0; u < 4; ++u)
                    mma16816(acc[t][u], af[t],
                             bfr[u >> 1][(u & 1) * 2], bfr[u >> 1][(u & 1) * 2 + 1]);
        }
    }

    // ---------- epilogue: stage via smem, write coalesced --------------------
    asm volatile("cp.async.wait_group 0;\n");
    __syncthreads();
    float* st = (float*)smem;                 // [128][129] fp32
    const float SC = 1.f / 15.f;
    const int row_ = lane >> 2, col_ = (lane & 3) * 2;
    #pragma unroll
    for (int t = 0; t < 4; ++t)
        #pragma unroll
        for (int u = 0; u < 4; ++u)
            #pragma unroll
            for (int e = 0; e < 4; ++e) {
                int ml = wm + t * 16 + row_ + ((e >> 1) ? 8 : 0);
                int nl = wn + u * 8 + col_ + (e & 1);
                st[ml * 129 + nl] = acc[t][u][e] * SC;
            }
    __syncthreads();

    // each warp owns 16 n-rows; per n, lanes cover contiguous m (coalesced)
    #pragma unroll 1
    for (int q = 0; q < 16; ++q) {
        int nl = wid * 16 + q;
        int n = n0b + nl;
        if (MODE == 1) {
            #pragma unroll
            for (int j = 0; j < 4; ++j) {
                int ml = j * 32 + lane;
                float v = fmaxf(st[ml * 129 + nl], 0.f);
                __nv_bfloat16 h = __float2bfloat16(v);
                int m = m0b + ml;
                outp[(size_t)n * MPIX + m] = h;                       // hi plane
                outp[(size_t)(N + n) * MPIX + m] =
                    __float2bfloat16(v - __bfloat162float(h));         // lo plane
            }
        } else {
            #pragma unroll
            for (int j = 0; j < 4; ++j) {
                int ml = j * 32 + lane;
                int m = m0b + ml;
                int b = m / HWOUT, s = m - b * HWOUT;
                size_t idx = ((size_t)b * COUT + n) * HWOUT + s;
                float v = st[ml * 129 + nl];
                if (MODE == 0) {
                    outf[idx] = v;
                } else {
                    v += resid[idx];
                    v = fminf(fmaxf(v, 0.f), 1.f);
                    outf[idx] = rintf(v * 15.f) * SC;
                }
            }
        }
    }
}

// ------------- depthwise 7x7 + BN1 -> hi/lo planes ---------------------------
__global__ void dwconv_kernel(const float* __restrict__ bg, const float* __restrict__ bb,
                              const float* __restrict__ bm, const float* __restrict__ bv) {
    __shared__ float tile[34 * 34];
    __shared__ float w[49];
    int bc = blockIdx.x;
    int c = bc & (COUT - 1);
    int b = bc >> 8;
    const float* plane = g_t0 + (size_t)bc * HWOUT;
    int tid = threadIdx.x;
    for (int idx = tid; idx < 34 * 34; idx += 256) {
        int rr = idx / 34, cc = idx - rr * 34;
        int ih = rr - 3, iw = cc - 3;
        tile[idx] = (ih >= 0 && ih < HOUT && iw >= 0 && iw < HOUT)
                        ? plane[ih * HOUT + iw] : 0.f;
    }
    if (tid < 49) w[tid] = g_W1f[c * 49 + tid];
    __syncthreads();
    float inv  = bg[c] / sqrtf(bv[c] + EPS_BN);
    float bias = bb[c] - bm[c] * inv;
    for (int s = tid; s < HWOUT; s += 256) {
        int oh = s / HOUT, ow = s - oh * HOUT;
        float sum = 0.f;
        #pragma unroll
        for (int i = 0; i < 7; i++)
            #pragma unroll
            for (int j = 0; j < 7; j++)
                sum = fmaf(tile[(oh + i) * 34 + ow + j], w[i * 7 + j], sum);
        float y = sum * inv + bias;
        __nv_bfloat16 h = __float2bfloat16(y);
        int m = b * HWOUT + s;
        g_t1[(size_t)c * MPIX + m] = h;                                  // hi plane
        g_t1[(size_t)(COUT + c) * MPIX + m] =
            __float2bfloat16(y - __bfloat162float(h));                    // lo plane
    }
}

// ------------- launch --------------------------------------------------------
extern "C" void kernel_launch(void* const* d_in, const int* in_sizes, int n_in,
                              void* d_out, int out_size) {
    const float* x     = (const float*)d_in[0];
    const float* bn0_g = (const float*)d_in[1];
    const float* bn0_b = (const float*)d_in[2];
    const float* bn0_m = (const float*)d_in[3];
    const float* bn0_v = (const float*)d_in[4];
    const float* Wd    = (const float*)d_in[5];
    const float* W1    = (const float*)d_in[6];
    const float* bn1_g = (const float*)d_in[7];
    const float* bn1_b = (const float*)d_in[8];
    const float* bn1_m = (const float*)d_in[9];
    const float* bn1_v = (const float*)d_in[10];
    const float* W2    = (const float*)d_in[11];
    const float* W3    = (const float*)d_in[12];
    float* out = (float*)d_out;

    void *pA, *pT0, *pT1, *pT2, *pWd, *pW2, *pW3, *pMax;
    cudaGetSymbolAddress(&pA,  g_A);
    cudaGetSymbolAddress(&pT0, g_t0);
    cudaGetSymbolAddress(&pT1, g_t1);
    cudaGetSymbolAddress(&pT2, g_t2);
    cudaGetSymbolAddress(&pWd, g_Wd);
    cudaGetSymbolAddress(&pW2, g_W2);
    cudaGetSymbolAddress(&pW3, g_W3);
    cudaGetSymbolAddress(&pMax, g_max);

    cudaFuncSetAttribute(mma_gemm<0>, cudaFuncAttributeMaxDynamicSharedMemorySize, SM_GEMM);
    cudaFuncSetAttribute(mma_gemm<1>, cudaFuncAttributeMaxDynamicSharedMemorySize, SM_GEMM);
    cudaFuncSetAttribute(mma_gemm<2>, cudaFuncAttributeMaxDynamicSharedMemorySize, SM_GEMM);

    // weight max
    cudaMemsetAsync(pMax, 0, 16);
    max4_kernel<<<dim3(64, 4), 256>>>(Wd, W1, W2, W3);

    // fused: im2col + all weight quantization (independent, co-scheduled)
    prep_kernel<<<dim3(98, 256 + Q_SLICES), 256>>>(
        x, bn0_g, bn0_b, bn0_m, bn0_v, Wd, W2, W3, W1);

    // conv1: M=25088, N=256, K=512  (grid: n fast, m slow)
    mma_gemm<0><<<dim3(COUT / BN, MPIX / BM), 256, SM_GEMM>>>(
        (const __nv_bfloat16*)pA, (size_t)KL1 * MPIX, (const __nv_bfloat16*)pWd,
        KL1, COUT, (float*)pT0, nullptr, nullptr);

    // depthwise + BN1
    dwconv_kernel<<<BATCH * COUT, 256>>>(bn1_g, bn1_b, bn1_m, bn1_v);

    // expand: N=1024, K=256
    mma_gemm<1><<<dim3(CEXP / BN, MPIX / BM), 256, SM_GEMM>>>(
        (const __nv_bfloat16*)pT1, (size_t)COUT * MPIX, (const __nv_bfloat16*)pW2,
        COUT, CEXP, nullptr, (__nv_bfloat16*)pT2, nullptr);

    // project: N=256, K=1024, + residual + q4
    mma_gemm<2><<<dim3(COUT / BN, MPIX / BM), 256, SM_GEMM>>>(
        (const __nv_bfloat16*)pT2, (size_t)CEXP * MPIX, (const __nv_bfloat16*)pW3,
        CEXP, COUT, out, nullptr, (const float*)pT0);
}

// round 16
// speedup vs baseline: 1.2566x; 1.1472x over previous
#include <cuda_runtime.h>
#include <cuda_bf16.h>
#include <cstdint>

#define EPS_BN 1e-5f

#define BATCH   32
#define CIN     128
#define COUT    256
#define CEXP    1024
#define HOUT    28
#define HWOUT   784
#define MPIX    25088          // BATCH*HWOUT, divisible by 128
#define KL1     512            // conv1 logical K (CIN*2*2)

// ------------- scratch (device globals) -------------------------------------
// activations: TWO planes, hi [K][M] then lo [K][M]
__device__ __nv_bfloat16 g_A [(size_t)2 * KL1  * MPIX];   // conv1 A   (51.4 MB)
__device__ float         g_t0[(size_t)BATCH * COUT * HWOUT]; // conv1 out NCHW
__device__ __nv_bfloat16 g_t1[(size_t)2 * COUT * MPIX];   // dw out planes
__device__ __nv_bfloat16 g_t2[(size_t)2 * CEXP * MPIX];   // expand out planes
__device__ __nv_bfloat16 g_Wd[KL1  * COUT];               // 15*w, [K][N], no dup
__device__ float         g_W1f[COUT * 49];
__device__ __nv_bfloat16 g_W2[COUT * CEXP];
__device__ __nv_bfloat16 g_W3[CEXP * COUT];
__device__ unsigned g_max[4];

// ------------- helpers -------------------------------------------------------
__device__ __forceinline__ void ldmx4t(uint32_t& r0, uint32_t& r1, uint32_t& r2,
                                       uint32_t& r3, uint32_t addr) {
    asm volatile("ldmatrix.sync.aligned.m8n8.x4.trans.shared.b16 {%0,%1,%2,%3},[%4];"
                 : "=r"(r0), "=r"(r1), "=r"(r2), "=r"(r3) : "r"(addr));
}

__device__ __forceinline__ void mma16816(float c[4], const uint32_t a[4],
                                         uint32_t b0, uint32_t b1) {
    asm volatile("mma.sync.aligned.m16n8k16.row.col.f32.bf16.bf16.f32 "
                 "{%0,%1,%2,%3},{%4,%5,%6,%7},{%8,%9},{%0,%1,%2,%3};"
                 : "+f"(c[0]), "+f"(c[1]), "+f"(c[2]), "+f"(c[3])
                 : "r"(a[0]), "r"(a[1]), "r"(a[2]), "r"(a[3]), "r"(b0), "r"(b1));
}

__device__ __forceinline__ void cp16(uint32_t s, const void* g) {
    asm volatile("cp.async.cg.shared.global [%0],[%1],16;\n" :: "r"(s), "l"(g));
}
#define CP_COMMIT() asm volatile("cp.async.commit_group;\n")

// ------------- weight max (tanh) ---------------------------------------------
__global__ void max4_kernel(const float* __restrict__ w0, const float* __restrict__ w1,
                            const float* __restrict__ w2, const float* __restrict__ w3) {
    int slot = blockIdx.y;
    const float* w; int n;
    if      (slot == 0) { w = w0; n = COUT * KL1; }
    else if (slot == 1) { w = w1; n = COUT * 49; }
    else if (slot == 2) { w = w2; n = CEXP * COUT; }
    else                { w = w3; n = COUT * CEXP; }
    float lm = 0.f;
    for (int i = blockIdx.x * blockDim.x + threadIdx.x; i < n;
         i += gridDim.x * blockDim.x)
        lm = fmaxf(lm, fabsf(tanhf(w[i])));
    #pragma unroll
    for (int o = 16; o > 0; o >>= 1)
        lm = fmaxf(lm, __shfl_xor_sync(0xffffffffu, lm, o));
    if ((threadIdx.x & 31) == 0) atomicMax(&g_max[slot], __float_as_uint(lm));
}

// ------------- fused prep: im2col (y<256) + weight quant (y>=256) ------------
#define QN_WD (COUT * KL1)          // 131072
#define QN_W2 (CEXP * COUT)         // 262144
#define QN_W3 (COUT * CEXP)         // 262144
#define QN_W1 (COUT * 49)           // 12544
#define QN_TOT (QN_WD + QN_W2 + QN_W3 + QN_W1)   // 667904
#define Q_SLICES ((QN_TOT + MPIX - 1) / MPIX)    // 27

__global__ void prep_kernel(const float* __restrict__ x,
                            const float* __restrict__ bg, const float* __restrict__ bb,
                            const float* __restrict__ bm, const float* __restrict__ bv,
                            const float* __restrict__ Wd, const float* __restrict__ W2,
                            const float* __restrict__ W3, const float* __restrict__ W1) {
    if (blockIdx.y < 256) {
        int m = blockIdx.x * 256 + threadIdx.x;
        int cd = blockIdx.y;
        int c = cd >> 1, dy = cd & 1;
        int b = m / HWOUT, s = m - b * HWOUT;
        int oh = s / HOUT, ow = s - oh * HOUT;
        float2 v2 = *(const float2*)(x + (((size_t)b * CIN + c) * 56 + oh * 2 + dy) * 56
                                       + ow * 2);
        float inv  = bg[c] / sqrtf(bv[c] + EPS_BN);
        float bias = bb[c] - bm[c] * inv;
        int kbase = 4 * c + 2 * dy;
        #pragma unroll
        for (int dx = 0; dx < 2; dx++) {
            float v = dx ? v2.y : v2.x;
            float y = fminf(fmaxf(v * inv + bias, 0.f), 1.f);
            y = rintf(y * 65535.f) / 65535.f;
            __nv_bfloat16 h = __float2bfloat16(y);
            int k = kbase + dx;
            g_A[(size_t)k * MPIX + m] = h;
            g_A[(size_t)(KL1 + k) * MPIX + m] =
                __float2bfloat16(y - __bfloat162float(h));
        }
        return;
    }
    int i = (blockIdx.y - 256) * MPIX + blockIdx.x * 256 + threadIdx.x;
    if (i < QN_WD) {
        float mx = __uint_as_float(g_max[0]);
        int n = i / KL1, k = i - n * KL1;
        float t = tanhf(Wd[i]) / (2.f * mx) + 0.5f;
        g_Wd[(size_t)k * COUT + n] = __float2bfloat16(2.f * rintf(t * 15.f) - 15.f);
        return;
    }
    i -= QN_WD;
    if (i < QN_W2) {
        float mx = __uint_as_float(g_max[2]);
        int n = i / COUT, k = i - n * COUT;
        float t = tanhf(W2[i]) / (2.f * mx) + 0.5f;
        g_W2[(size_t)k * CEXP + n] = __float2bfloat16(2.f * rintf(t * 15.f) - 15.f);
        return;
    }
    i -= QN_W2;
    if (i < QN_W3) {
        float mx = __uint_as_float(g_max[3]);
        int n = i / CEXP, k = i - n * CEXP;
        float t = tanhf(W3[i]) / (2.f * mx) + 0.5f;
        g_W3[(size_t)k * COUT + n] = __float2bfloat16(2.f * rintf(t * 15.f) - 15.f);
        return;
    }
    i -= QN_W3;
    if (i < QN_W1) {
        float mx = __uint_as_float(g_max[1]);
        float t = tanhf(W1[i]) / (2.f * mx) + 0.5f;
        g_W1f[i] = 2.f * (rintf(t * 15.f) / 15.f) - 1.f;
    }
}

// ------------- tensor-core GEMM: hi/lo planes share B fragments --------------
#define BM 128
#define BN 128
#define BKL 16
#define LDSA 136
#define STAGES 5
#define A_BYTES (32 * LDSA * 2)           // 8704
#define B_BYTES (16 * LDSA * 2)           // 4352
#define STG_BYTES (A_BYTES + B_BYTES)     // 13056
#define SM_GEMM 66560

template<int MODE>
__global__ void __launch_bounds__(256)
mma_gemm(const __nv_bfloat16* __restrict__ A, size_t aplane,
         const __nv_bfloat16* __restrict__ B,
         int K, int N, float* __restrict__ outf, __nv_bfloat16* __restrict__ outp,
         const float* __restrict__ resid) {
    extern __shared__ char smem[];
    const int tid = threadIdx.x;
    const int lane = tid & 31, wid = tid >> 5;
    const int m0b = blockIdx.y * BM, n0b = blockIdx.x * BN;
    const int wm = (wid & 1) * 64;
    const int wn = (wid >> 1) * 32;

    float acc[4][4][4];
    #pragma unroll
    for (int t = 0; t < 4; t++)
        #pragma unroll
        for (int u = 0; u < 4; u++)
            #pragma unroll
            for (int e = 0; e < 4; e++) acc[t][u][e] = 0.f;

    const int ra = tid >> 4, ca = (tid & 15) * 8;
    const uint32_t sbase = (uint32_t)__cvta_generic_to_shared(smem);
    const uint32_t a_off = (ra * LDSA + ca) * 2;

    const int g = lane >> 3, r = lane & 7;
    const int a_row0 = ((g >> 1) << 3) + r;
    const int a_col  = wm + ((g & 1) << 3);
    const int b_row0 = ((g & 1) << 3) + r;
    const int b_col0 = wn + ((g >> 1) << 3);

    const int iters = K / BKL;

    auto load_tile = [&](int it) {
        if (it < iters) {
            const int kb = it * BKL;
            const uint32_t sa = sbase + (it % STAGES) * STG_BYTES;
            const __nv_bfloat16* ag = A + (size_t)(kb + ra) * MPIX + m0b + ca;
            cp16(sa + a_off, ag);                                  // hi
            cp16(sa + a_off + 16 * LDSA * 2, ag + aplane);         // lo
            cp16(sa + A_BYTES + a_off, B + (size_t)(kb + ra) * N + n0b + ca);
        }
        CP_COMMIT();
    };

    load_tile(0);
    load_tile(1);
    load_tile(2);
    load_tile(3);

    for (int it = 0; it < iters; ++it) {
        asm volatile("cp.async.wait_group 3;\n");
        __syncthreads();
        load_tile(it + 4);

        const uint32_t ab = sbase + (it % STAGES) * STG_BYTES;
        const uint32_t bb = ab + A_BYTES;
        uint32_t bfr[2][4];
        #pragma unroll
        for (int pq = 0; pq < 2; ++pq)
            ldmx4t(bfr[pq][0], bfr[pq][1], bfr[pq][2], bfr[pq][3],
                   bb + (b_row0 * LDSA + b_col0 + pq * 16) * 2);
        #pragma unroll
        for (int pl = 0; pl < 2; ++pl) {
            uint32_t af[4][4];
            #pragma unroll
            for (int t = 0; t < 4; ++t)
                ldmx4t(af[t][0], af[t][1], af[t][2], af[t][3],
                       ab + ((pl * 16 + a_row0) * LDSA + a_col + t * 16) * 2);
            #pragma unroll
            for (int t = 0; t < 4; ++t)
                #pragma unroll
                for (int u = 0; u < 4; ++u)
                    mma16816(acc[t][u], af[t],
                             bfr[u >> 1][(u & 1) * 2], bfr[u >> 1][(u & 1) * 2 + 1]);
        }
    }

    // ---------- epilogue: stage via smem, write coalesced --------------------
    asm volatile("cp.async.wait_group 0;\n");
    __syncthreads();
    float* st = (float*)smem;                 // [128][129] fp32
    const float SC = 1.f / 15.f;
    const int row_ = lane >> 2, col_ = (lane & 3) * 2;
    #pragma unroll
    for (int t = 0; t < 4; ++t)
        #pragma unroll
        for (int u = 0; u < 4; ++u)
            #pragma unroll
            for (int e = 0; e < 4; ++e) {
                int ml = wm + t * 16 + row_ + ((e >> 1) ? 8 : 0);
                int nl = wn + u * 8 + col_ + (e & 1);
                st[ml * 129 + nl] = acc[t][u][e] * SC;
            }
    __syncthreads();

    #pragma unroll 1
    for (int q = 0; q < 16; ++q) {
        int nl = wid * 16 + q;
        int n = n0b + nl;
        if (MODE == 1) {
            #pragma unroll
            for (int j = 0; j < 4; ++j) {
                int ml = j * 32 + lane;
                float v = fmaxf(st[ml * 129 + nl], 0.f);
                __nv_bfloat16 h = __float2bfloat16(v);
                int m = m0b + ml;
                outp[(size_t)n * MPIX + m] = h;
                outp[(size_t)(N + n) * MPIX + m] =
                    __float2bfloat16(v - __bfloat162float(h));
            }
        } else {
            #pragma unroll
            for (int j = 0; j < 4; ++j) {
                int ml = j * 32 + lane;
                int m = m0b + ml;
                int b = m / HWOUT, s = m - b * HWOUT;
                size_t idx = ((size_t)b * COUT + n) * HWOUT + s;
                float v = st[ml * 129 + nl];
                if (MODE == 0) {
                    outf[idx] = v;
                } else {
                    v += resid[idx];
                    v = fminf(fmaxf(v, 0.f), 1.f);
                    outf[idx] = rintf(v * 15.f) * SC;
                }
            }
        }
    }
}

// ------------- depthwise 7x7 + BN1, 4x vertical register blocking ------------
__global__ void dwconv_kernel(const float* __restrict__ bg, const float* __restrict__ bb,
                              const float* __restrict__ bm, const float* __restrict__ bv) {
    __shared__ float tile[34 * 34];
    __shared__ float w[49];
    int bc = blockIdx.x;
    int c = bc & (COUT - 1);
    int b = bc >> 8;
    const float* plane = g_t0 + (size_t)bc * HWOUT;
    int tid = threadIdx.x;
    for (int idx = tid; idx < 34 * 34; idx += 256) {
        int rr = idx / 34, cc = idx - rr * 34;
        int ih = rr - 3, iw = cc - 3;
        tile[idx] = (ih >= 0 && ih < HOUT && iw >= 0 && iw < HOUT)
                        ? plane[ih * HOUT + iw] : 0.f;
    }
    if (tid < 49) w[tid] = g_W1f[c * 49 + tid];
    __syncthreads();
    if (tid >= 196) return;                    // 28 ow x 7 oh-groups
    int ow  = tid % 28;
    int oh0 = (tid / 28) * 4;                  // 4 vertical outputs per thread
    float inv  = bg[c] / sqrtf(bv[c] + EPS_BN);
    float bias = bb[c] - bm[c] * inv;

    float a0 = 0.f, a1 = 0.f, a2 = 0.f, a3 = 0.f;
    #pragma unroll
    for (int rr = 0; rr < 10; rr++) {          // tile rows oh0..oh0+9
        float rowv[7];
        #pragma unroll
        for (int j = 0; j < 7; j++) rowv[j] = tile[(oh0 + rr) * 34 + ow + j];
        #pragma unroll
        for (int j = 0; j < 7; j++) {
            if (rr < 7)            a0 = fmaf(rowv[j], w[rr * 7 + j], a0);
            if (rr >= 1 && rr < 8) a1 = fmaf(rowv[j], w[(rr - 1) * 7 + j], a1);
            if (rr >= 2 && rr < 9) a2 = fmaf(rowv[j], w[(rr - 2) * 7 + j], a2);
            if (rr >= 3)           a3 = fmaf(rowv[j], w[(rr - 3) * 7 + j], a3);
        }
    }

    float accs[4] = {a0, a1, a2, a3};
    #pragma unroll
    for (int q = 0; q < 4; q++) {
        float y = accs[q] * inv + bias;
        __nv_bfloat16 h = __float2bfloat16(y);
        int m = b * HWOUT + (oh0 + q) * HOUT + ow;
        g_t1[(size_t)c * MPIX + m] = h;                                  // hi plane
        g_t1[(size_t)(COUT + c) * MPIX + m] =
            __float2bfloat16(y - __bfloat162float(h));                    // lo plane
    }
}

// ------------- launch --------------------------------------------------------
extern "C" void kernel_launch(void* const* d_in, const int* in_sizes, int n_in,
                              void* d_out, int out_size) {
    const float* x     = (const float*)d_in[0];
    const float* bn0_g = (const float*)d_in[1];
    const float* bn0_b = (const float*)d_in[2];
    const float* bn0_m = (const float*)d_in[3];
    const float* bn0_v = (const float*)d_in[4];
    const float* Wd    = (const float*)d_in[5];
    const float* W1    = (const float*)d_in[6];
    const float* bn1_g = (const float*)d_in[7];
    const float* bn1_b = (const float*)d_in[8];
    const float* bn1_m = (const float*)d_in[9];
    const float* bn1_v = (const float*)d_in[10];
    const float* W2    = (const float*)d_in[11];
    const float* W3    = (const float*)d_in[12];
    float* out = (float*)d_out;

    void *pA, *pT0, *pT1, *pT2, *pWd, *pW2, *pW3, *pMax;
    cudaGetSymbolAddress(&pA,  g_A);
    cudaGetSymbolAddress(&pT0, g_t0);
    cudaGetSymbolAddress(&pT1, g_t1);
    cudaGetSymbolAddress(&pT2, g_t2);
    cudaGetSymbolAddress(&pWd, g_Wd);
    cudaGetSymbolAddress(&pW2, g_W2);
    cudaGetSymbolAddress(&pW3, g_W3);
    cudaGetSymbolAddress(&pMax, g_max);

    cudaFuncSetAttribute(mma_gemm<0>, cudaFuncAttributeMaxDynamicSharedMemorySize, SM_GEMM);
    cudaFuncSetAttribute(mma_gemm<1>, cudaFuncAttributeMaxDynamicSharedMemorySize, SM_GEMM);
    cudaFuncSetAttribute(mma_gemm<2>, cudaFuncAttributeMaxDynamicSharedMemorySize, SM_GEMM);

    // weight max
    cudaMemsetAsync(pMax, 0, 16);
    max4_kernel<<<dim3(64, 4), 256>>>(Wd, W1, W2, W3);

    // fused: im2col + all weight quantization
    prep_kernel<<<dim3(98, 256 + Q_SLICES), 256>>>(
        x, bn0_g, bn0_b, bn0_m, bn0_v, Wd, W2, W3, W1);

    // conv1: M=25088, N=256, K=512
    mma_gemm<0><<<dim3(COUT / BN, MPIX / BM), 256, SM_GEMM>>>(
        (const __nv_bfloat16*)pA, (size_t)KL1 * MPIX, (const __nv_bfloat16*)pWd,
        KL1, COUT, (float*)pT0, nullptr, nullptr);

    // depthwise + BN1 (register-blocked)
    dwconv_kernel<<<BATCH * COUT, 256>>>(bn1_g, bn1_b, bn1_m, bn1_v);

    // expand: N=1024, K=256
    mma_gemm<1><<<dim3(CEXP / BN, MPIX / BM), 256, SM_GEMM>>>(
        (const __nv_bfloat16*)pT1, (size_t)COUT * MPIX, (const __nv_bfloat16*)pW2,
        COUT, CEXP, nullptr, (__nv_bfloat16*)pT2, nullptr);

    // project: N=256, K=1024, + residual + q4
    mma_gemm<2><<<dim3(COUT / BN, MPIX / BM), 256, SM_GEMM>>>(
        (const __nv_bfloat16*)pT2, (size_t)CEXP * MPIX, (const __nv_bfloat16*)pW3,
        CEXP, COUT, out, nullptr, (const float*)pT0);
}

// round 17
// speedup vs baseline: 1.2651x; 1.0067x over previous
#include <cuda_runtime.h>
#include <cuda_bf16.h>
#include <cstdint>

#define EPS_BN 1e-5f

#define BATCH   32
#define CIN     128
#define COUT    256
#define CEXP    1024
#define HOUT    28
#define HWOUT   784
#define MPIX    25088          // BATCH*HWOUT, divisible by 128
#define KL1     512            // conv1 logical K (CIN*2*2)

// ------------- scratch (device globals) -------------------------------------
// activations: TWO planes, hi [K][M] then lo [K][M]
__device__ __nv_bfloat16 g_A [(size_t)2 * KL1  * MPIX];   // conv1 A   (51.4 MB)
__device__ float         g_t0[(size_t)BATCH * COUT * HWOUT]; // conv1 out NCHW
__device__ __nv_bfloat16 g_t1[(size_t)2 * COUT * MPIX];   // dw out planes
__device__ __nv_bfloat16 g_t2[(size_t)2 * CEXP * MPIX];   // expand out planes
__device__ __nv_bfloat16 g_Wd[KL1  * COUT];               // 15*w, [K][N], no dup
__device__ float         g_W1f[COUT * 49];
__device__ __nv_bfloat16 g_W2[COUT * CEXP];
__device__ __nv_bfloat16 g_W3[CEXP * COUT];
__device__ unsigned g_max[4];

// ------------- helpers -------------------------------------------------------
__device__ __forceinline__ void ldmx4t(uint32_t& r0, uint32_t& r1, uint32_t& r2,
                                       uint32_t& r3, uint32_t addr) {
    asm volatile("ldmatrix.sync.aligned.m8n8.x4.trans.shared.b16 {%0,%1,%2,%3},[%4];"
                 : "=r"(r0), "=r"(r1), "=r"(r2), "=r"(r3) : "r"(addr));
}

__device__ __forceinline__ void mma16816(float c[4], const uint32_t a[4],
                                         uint32_t b0, uint32_t b1) {
    asm volatile("mma.sync.aligned.m16n8k16.row.col.f32.bf16.bf16.f32 "
                 "{%0,%1,%2,%3},{%4,%5,%6,%7},{%8,%9},{%0,%1,%2,%3};"
                 : "+f"(c[0]), "+f"(c[1]), "+f"(c[2]), "+f"(c[3])
                 : "r"(a[0]), "r"(a[1]), "r"(a[2]), "r"(a[3]), "r"(b0), "r"(b1));
}

__device__ __forceinline__ void cp16(uint32_t s, const void* g) {
    asm volatile("cp.async.cg.shared.global [%0],[%1],16;\n" :: "r"(s), "l"(g));
}
#define CP_COMMIT() asm volatile("cp.async.commit_group;\n")

// ------------- fused stage 1: im2col + weight max ----------------------------
// blockIdx.y < 256 : im2col (BN0 + q16 -> hi/lo planes)
// blockIdx.y >= 256: tanh-max reduction slice for slot (y-256)
__global__ void prepA_kernel(const float* __restrict__ x,
                             const float* __restrict__ bg, const float* __restrict__ bb,
                             const float* __restrict__ bm, const float* __restrict__ bv,
                             const float* __restrict__ Wd, const float* __restrict__ W1,
                             const float* __restrict__ W2, const float* __restrict__ W3) {
    if (blockIdx.y < 256) {
        int m = blockIdx.x * 256 + threadIdx.x;   // 98 x-blocks -> exactly MPIX
        int cd = blockIdx.y;
        int c = cd >> 1, dy = cd & 1;
        int b = m / HWOUT, s = m - b * HWOUT;
        int oh = s / HOUT, ow = s - oh * HOUT;
        float2 v2 = *(const float2*)(x + (((size_t)b * CIN + c) * 56 + oh * 2 + dy) * 56
                                       + ow * 2);
        float inv  = bg[c] / sqrtf(bv[c] + EPS_BN);
        float bias = bb[c] - bm[c] * inv;
        int kbase = 4 * c + 2 * dy;
        #pragma unroll
        for (int dx = 0; dx < 2; dx++) {
            float v = dx ? v2.y : v2.x;
            float y = fminf(fmaxf(v * inv + bias, 0.f), 1.f);
            y = rintf(y * 65535.f) / 65535.f;
            __nv_bfloat16 h = __float2bfloat16(y);
            int k = kbase + dx;
            g_A[(size_t)k * MPIX + m] = h;
            g_A[(size_t)(KL1 + k) * MPIX + m] =
                __float2bfloat16(y - __bfloat162float(h));
        }
        return;
    }
    // ---- weight max slices (slot per y) ----
    int slot = blockIdx.y - 256;
    const float* w; int n;
    if      (slot == 0) { w = Wd; n = COUT * KL1; }
    else if (slot == 1) { w = W1; n = COUT * 49; }
    else if (slot == 2) { w = W2; n = CEXP * COUT; }
    else                { w = W3; n = COUT * CEXP; }
    float lm = 0.f;
    for (int i = blockIdx.x * 256 + threadIdx.x; i < n; i += 98 * 256)
        lm = fmaxf(lm, fabsf(tanhf(w[i])));
    #pragma unroll
    for (int o = 16; o > 0; o >>= 1)
        lm = fmaxf(lm, __shfl_xor_sync(0xffffffffu, lm, o));
    if ((threadIdx.x & 31) == 0) atomicMax(&g_max[slot], __float_as_uint(lm));
}

// ------------- stage 2: weight quantization ----------------------------------
#define QN_WD (COUT * KL1)
#define QN_W2 (CEXP * COUT)
#define QN_W3 (COUT * CEXP)
#define QN_W1 (COUT * 49)

__global__ void quantW_all(const float* __restrict__ Wd, const float* __restrict__ W2,
                           const float* __restrict__ W3, const float* __restrict__ W1) {
    int which = blockIdx.y;
    int i = blockIdx.x * 256 + threadIdx.x;
    if (which == 3) {
        if (i >= QN_W1) return;
        float mx = __uint_as_float(g_max[1]);
        float t = tanhf(W1[i]) / (2.f * mx) + 0.5f;
        g_W1f[i] = 2.f * (rintf(t * 15.f) / 15.f) - 1.f;
        return;
    }
    const float* src; __nv_bfloat16* dst; int N, K, slot;
    if      (which == 0) { src = Wd; dst = g_Wd; N = COUT; K = KL1;  slot = 0; }
    else if (which == 1) { src = W2; dst = g_W2; N = CEXP; K = COUT; slot = 2; }
    else                 { src = W3; dst = g_W3; N = COUT; K = CEXP; slot = 3; }
    if (i >= N * K) return;
    int n = i / K, k = i - n * K;
    float mx = __uint_as_float(g_max[slot]);
    float t  = tanhf(src[i]) / (2.f * mx) + 0.5f;
    dst[(size_t)k * N + n] = __float2bfloat16(2.f * rintf(t * 15.f) - 15.f);
}

// ------------- tensor-core GEMM: hi/lo planes share B fragments --------------
#define BM 128
#define BN 128
#define BKL 16
#define LDSA 136
#define STAGES 5
#define A_BYTES (32 * LDSA * 2)           // 8704
#define B_BYTES (16 * LDSA * 2)           // 4352
#define STG_BYTES (A_BYTES + B_BYTES)     // 13056
#define SM_GEMM 66560

template<int MODE>
__global__ void __launch_bounds__(256)
mma_gemm(const __nv_bfloat16* __restrict__ A, size_t aplane,
         const __nv_bfloat16* __restrict__ B,
         int K, int N, float* __restrict__ outf, __nv_bfloat16* __restrict__ outp,
         const float* __restrict__ resid) {
    extern __shared__ char smem[];
    const int tid = threadIdx.x;
    const int lane = tid & 31, wid = tid >> 5;
    const int m0b = blockIdx.y * BM, n0b = blockIdx.x * BN;
    const int wm = (wid & 1) * 64;
    const int wn = (wid >> 1) * 32;

    float acc[4][4][4];
    #pragma unroll
    for (int t = 0; t < 4; t++)
        #pragma unroll
        for (int u = 0; u < 4; u++)
            #pragma unroll
            for (int e = 0; e < 4; e++) acc[t][u][e] = 0.f;

    const int ra = tid >> 4, ca = (tid & 15) * 8;
    const uint32_t sbase = (uint32_t)__cvta_generic_to_shared(smem);
    const uint32_t a_off = (ra * LDSA + ca) * 2;

    const int g = lane >> 3, r = lane & 7;
    const int a_row0 = ((g >> 1) << 3) + r;
    const int a_col  = wm + ((g & 1) << 3);
    const int b_row0 = ((g & 1) << 3) + r;
    const int b_col0 = wn + ((g >> 1) << 3);

    const int iters = K / BKL;

    auto load_tile = [&](int it) {
        if (it < iters) {
            const int kb = it * BKL;
            const uint32_t sa = sbase + (it % STAGES) * STG_BYTES;
            const __nv_bfloat16* ag = A + (size_t)(kb + ra) * MPIX + m0b + ca;
            cp16(sa + a_off, ag);                                  // hi
            cp16(sa + a_off + 16 * LDSA * 2, ag + aplane);         // lo
            cp16(sa + A_BYTES + a_off, B + (size_t)(kb + ra) * N + n0b + ca);
        }
        CP_COMMIT();
    };

    load_tile(0);
    load_tile(1);
    load_tile(2);
    load_tile(3);

    for (int it = 0; it < iters; ++it) {
        asm volatile("cp.async.wait_group 3;\n");
        __syncthreads();
        load_tile(it + 4);

        const uint32_t ab = sbase + (it % STAGES) * STG_BYTES;
        const uint32_t bb = ab + A_BYTES;
        uint32_t bfr[2][4];
        #pragma unroll
        for (int pq = 0; pq < 2; ++pq)
            ldmx4t(bfr[pq][0], bfr[pq][1], bfr[pq][2], bfr[pq][3],
                   bb + (b_row0 * LDSA + b_col0 + pq * 16) * 2);
        #pragma unroll
        for (int pl = 0; pl < 2; ++pl) {
            uint32_t af[4][4];
            #pragma unroll
            for (int t = 0; t < 4; ++t)
                ldmx4t(af[t][0], af[t][1], af[t][2], af[t][3],
                       ab + ((pl * 16 + a_row0) * LDSA + a_col + t * 16) * 2);
            #pragma unroll
            for (int t = 0; t < 4; ++t)
                #pragma unroll
                for (int u = 0; u < 4; ++u)
                    mma16816(acc[t][u], af[t],
                             bfr[u >> 1][(u & 1) * 2], bfr[u >> 1][(u & 1) * 2 + 1]);
        }
    }

    // ---------- epilogue: stage via smem, write coalesced --------------------
    asm volatile("cp.async.wait_group 0;\n");
    __syncthreads();
    float* st = (float*)smem;                 // [128][129] fp32
    const float SC = 1.f / 15.f;
    const int row_ = lane >> 2, col_ = (lane & 3) * 2;
    #pragma unroll
    for (int t = 0; t < 4; ++t)
        #pragma unroll
        for (int u = 0; u < 4; ++u)
            #pragma unroll
            for (int e = 0; e < 4; ++e) {
                int ml = wm + t * 16 + row_ + ((e >> 1) ? 8 : 0);
                int nl = wn + u * 8 + col_ + (e & 1);
                st[ml * 129 + nl] = acc[t][u][e] * SC;
            }
    __syncthreads();

    #pragma unroll 1
    for (int q = 0; q < 16; ++q) {
        int nl = wid * 16 + q;
        int n = n0b + nl;
        if (MODE == 1) {
            #pragma unroll
            for (int j = 0; j < 4; ++j) {
                int ml = j * 32 + lane;
                float v = fmaxf(st[ml * 129 + nl], 0.f);
                __nv_bfloat16 h = __float2bfloat16(v);
                int m = m0b + ml;
                outp[(size_t)n * MPIX + m] = h;
                outp[(size_t)(N + n) * MPIX + m] =
                    __float2bfloat16(v - __bfloat162float(h));
            }
        } else {
            #pragma unroll
            for (int j = 0; j < 4; ++j) {
                int ml = j * 32 + lane;
                int m = m0b + ml;
                int b = m / HWOUT, s = m - b * HWOUT;
                size_t idx = ((size_t)b * COUT + n) * HWOUT + s;
                float v = st[ml * 129 + nl];
                if (MODE == 0) {
                    outf[idx] = v;
                } else {
                    v += resid[idx];
                    v = fminf(fmaxf(v, 0.f), 1.f);
                    outf[idx] = rintf(v * 15.f) * SC;
                }
            }
        }
    }
}

// ------------- depthwise 7x7 + BN1: 4x2 blocking, 2 planes/CTA ---------------
__global__ void __launch_bounds__(256)
dwconv_kernel(const float* __restrict__ bg, const float* __restrict__ bb,
              const float* __restrict__ bm, const float* __restrict__ bv) {
    __shared__ float tile[2][34 * 34];
    __shared__ float w[2][49];
    int tid = threadIdx.x;
    int bc0 = blockIdx.x * 2;
    for (int idx = tid; idx < 2 * 1156; idx += 256) {
        int p = idx / 1156, q = idx - p * 1156;
        int rr = q / 34, cc = q - rr * 34;
        int ih = rr - 3, iw = cc - 3;
        tile[p][q] = (ih >= 0 && ih < HOUT && iw >= 0 && iw < HOUT)
            ? g_t0[(size_t)(bc0 + p) * HWOUT + ih * HOUT + iw] : 0.f;
    }
    if (tid < 98) {
        int p = tid / 49, j = tid - p * 49;
        w[p][j] = g_W1f[((bc0 + p) & (COUT - 1)) * 49 + j];
    }
    __syncthreads();
    int p = tid >> 7;
    int wg = tid & 127;
    if (wg >= 98) return;                       // 14 ow-pairs x 7 oh-groups
    int bc = bc0 + p;
    int c = bc & (COUT - 1), b = bc >> 8;
    int ow0 = (wg % 14) * 2;
    int oh0 = (wg / 14) * 4;
    float inv  = bg[c] / sqrtf(bv[c] + EPS_BN);
    float bias = bb[c] - bm[c] * inv;

    float acc[4][2];
    #pragma unroll
    for (int q = 0; q < 4; q++) { acc[q][0] = 0.f; acc[q][1] = 0.f; }

    #pragma unroll
    for (int rr = 0; rr < 10; rr++) {           // tile rows oh0..oh0+9
        float rowv[8];
        #pragma unroll
        for (int j = 0; j < 8; j++) rowv[j] = tile[p][(oh0 + rr) * 34 + ow0 + j];
        #pragma unroll
        for (int j = 0; j < 7; j++) {
            if (rr < 7) {
                float wv = w[p][rr * 7 + j];
                acc[0][0] = fmaf(rowv[j], wv, acc[0][0]);
                acc[0][1] = fmaf(rowv[j + 1], wv, acc[0][1]);
            }
            if (rr >= 1 && rr < 8) {
                float wv = w[p][(rr - 1) * 7 + j];
                acc[1][0] = fmaf(rowv[j], wv, acc[1][0]);
                acc[1][1] = fmaf(rowv[j + 1], wv, acc[1][1]);
            }
            if (rr >= 2 && rr < 9) {
                float wv = w[p][(rr - 2) * 7 + j];
                acc[2][0] = fmaf(rowv[j], wv, acc[2][0]);
                acc[2][1] = fmaf(rowv[j + 1], wv, acc[2][1]);
            }
            if (rr >= 3) {
                float wv = w[p][(rr - 3) * 7 + j];
                acc[3][0] = fmaf(rowv[j], wv, acc[3][0]);
                acc[3][1] = fmaf(rowv[j + 1], wv, acc[3][1]);
            }
        }
    }

    #pragma unroll
    for (int q = 0; q < 4; q++)
        #pragma unroll
        for (int d = 0; d < 2; d++) {
            float y = acc[q][d] * inv + bias;
            __nv_bfloat16 h = __float2bfloat16(y);
            int m = b * HWOUT + (oh0 + q) * HOUT + ow0 + d;
            g_t1[(size_t)c * MPIX + m] = h;                              // hi plane
            g_t1[(size_t)(COUT + c) * MPIX + m] =
                __float2bfloat16(y - __bfloat162float(h));                // lo plane
        }
}

// ------------- launch --------------------------------------------------------
extern "C" void kernel_launch(void* const* d_in, const int* in_sizes, int n_in,
                              void* d_out, int out_size) {
    const float* x     = (const float*)d_in[0];
    const float* bn0_g = (const float*)d_in[1];
    const float* bn0_b = (const float*)d_in[2];
    const float* bn0_m = (const float*)d_in[3];
    const float* bn0_v = (const float*)d_in[4];
    const float* Wd    = (const float*)d_in[5];
    const float* W1    = (const float*)d_in[6];
    const float* bn1_g = (const float*)d_in[7];
    const float* bn1_b = (const float*)d_in[8];
    const float* bn1_m = (const float*)d_in[9];
    const float* bn1_v = (const float*)d_in[10];
    const float* W2    = (const float*)d_in[11];
    const float* W3    = (const float*)d_in[12];
    float* out = (float*)d_out;

    void *pA, *pT0, *pT1, *pT2, *pWd, *pW2, *pW3, *pMax;
    cudaGetSymbolAddress(&pA,  g_A);
    cudaGetSymbolAddress(&pT0, g_t0);
    cudaGetSymbolAddress(&pT1, g_t1);
    cudaGetSymbolAddress(&pT2, g_t2);
    cudaGetSymbolAddress(&pWd, g_Wd);
    cudaGetSymbolAddress(&pW2, g_W2);
    cudaGetSymbolAddress(&pW3, g_W3);
    cudaGetSymbolAddress(&pMax, g_max);

    cudaFuncSetAttribute(mma_gemm<0>, cudaFuncAttributeMaxDynamicSharedMemorySize, SM_GEMM);
    cudaFuncSetAttribute(mma_gemm<1>, cudaFuncAttributeMaxDynamicSharedMemorySize, SM_GEMM);
    cudaFuncSetAttribute(mma_gemm<2>, cudaFuncAttributeMaxDynamicSharedMemorySize, SM_GEMM);

    cudaMemsetAsync(pMax, 0, 16);

    // stage 1: im2col + weight-max (independent, co-scheduled)
    prepA_kernel<<<dim3(98, 260), 256>>>(x, bn0_g, bn0_b, bn0_m, bn0_v,
                                         Wd, W1, W2, W3);
    // stage 2: quantize all weights
    quantW_all<<<dim3(1024, 4), 256>>>(Wd, W2, W3, W1);

    // conv1: M=25088, N=256, K=512
    mma_gemm<0><<<dim3(COUT / BN, MPIX / BM), 256, SM_GEMM>>>(
        (const __nv_bfloat16*)pA, (size_t)KL1 * MPIX, (const __nv_bfloat16*)pWd,
        KL1, COUT, (float*)pT0, nullptr, nullptr);

    // depthwise + BN1 (4x2 blocked, 2 planes/CTA)
    dwconv_kernel<<<BATCH * COUT / 2, 256>>>(bn1_g, bn1_b, bn1_m, bn1_v);

    // expand: N=1024, K=256
    mma_gemm<1><<<dim3(CEXP / BN, MPIX / BM), 256, SM_GEMM>>>(
        (const __nv_bfloat16*)pT1, (size_t)COUT * MPIX, (const __nv_bfloat16*)pW2,
        COUT, CEXP, nullptr, (__nv_bfloat16*)pT2, nullptr);

    // project: N=256, K=1024, + residual + q4
    mma_gemm<2><<<dim3(COUT / BN, MPIX / BM), 256, SM_GEMM>>>(
        (const __nv_bfloat16*)pT2, (size_t)CEXP * MPIX, (const __nv_bfloat16*)pW3,
        CEXP, COUT, out, nullptr, (const float*)pT0);
}